// round 16
// baseline (speedup 1.0000x reference)
#include <cuda_runtime.h>
#include <cmath>

#define Pdim 160
#define PP (Pdim*Pdim)          // 25600
#define Bn 4
#define Cc 3
#define Hh 32
#define NDIM (Cc*PP)            // 76800
#define NX (Bn*NDIM)            // 307200

typedef unsigned long long u64;

__device__ __forceinline__ void upk2(u64 v, float& lo, float& hi) {
    asm("mov.b64 {%0,%1},%2;" : "=f"(lo), "=f"(hi) : "l"(v));
}
// packed fp32x2 FMA (SASS FFMA2): 2 exact fp32 FMAs per issue slot
__device__ __forceinline__ u64 ffma2(u64 a, u64 b, u64 c) {
    u64 d; asm("fma.rn.f32x2 %0,%1,%2,%3;" : "=l"(d) : "l"(a), "l"(b), "l"(c));
    return d;
}
__device__ __forceinline__ u64 fadd2(u64 a, u64 b) {
    u64 d; asm("add.rn.f32x2 %0,%1,%2;" : "=l"(d) : "l"(a), "l"(b));
    return d;
}
#define NEG1_X2 0xBF800000BF800000ULL
__device__ __forceinline__ u64 fsub2(u64 a, u64 b) {   // a - b (exact)
    return ffma2(b, NEG1_X2, a);
}

// ---------------- scratch (static device globals; no allocs allowed) -------
__device__ float g_x[NX];
__device__ float g_xe[NX];
__device__ float g_acc[NX];
__device__ float g_pre1[Bn*Hh*PP];        // act1 = relu(conv1 pre-act), primal
__device__ float g_t1[Bn*Hh*PP];          // t1 = mask(pre1) * v1, tangent
__device__ float g_v1[Hh*PP];             // conv1(eps), loop-invariant tangent
__device__ float g_pre2[2*Bn*Hh*PP];      // [0..4): primal pre2, [4..8): tangent v2
__device__ float g_part[Bn*100];          // scaled divergence partials (accumulated)
__device__ float g_seps;
// pre-transposed / pre-transformed weights (filled once per replay)
__device__ float  g_w1t[Cc*9*Hh];         // [cin][j][oc]
__device__ float  g_w2u[Hh*Hh*16];        // Winograd U = G g G^T: [cin][oc][pos16]
__device__ float2 g_w3t[Hh*9*4];          // [cin][j][oc pad4] dup {w,w}

// ---------------- weight transpose / Winograd transform (once per replay) --
__global__ void prep_weights(const float* __restrict__ w1,
                             const float* __restrict__ w2,
                             const float* __restrict__ w3)
{
    int tid = blockIdx.x * 256 + threadIdx.x;
    int nth = gridDim.x * 256;
    for (int i = tid; i < Cc*9*Hh; i += nth) {
        int cin = i / 288, r = i - cin*288, j = r >> 5, oc = r & 31;
        g_w1t[i] = w1[(oc*Cc + cin)*9 + j];
    }
    // Winograd F(2x2,3x3) weight transform for w2
    for (int i = tid; i < Hh*Hh; i += nth) {
        int cin = i >> 5, oc = i & 31;
        const float* g = w2 + (oc*Hh + cin)*9;
        float T[4][3];
        #pragma unroll
        for (int c = 0; c < 3; c++) {
            float g0 = g[c], g1 = g[3+c], g2 = g[6+c];
            T[0][c] = g0;
            T[1][c] = 0.5f*(g0 + g1 + g2);
            T[2][c] = 0.5f*(g0 - g1 + g2);
            T[3][c] = g2;
        }
        float* U = g_w2u + ((size_t)cin*Hh + oc)*16;
        #pragma unroll
        for (int r = 0; r < 4; r++) {
            float t0 = T[r][0], t1 = T[r][1], t2 = T[r][2];
            U[r*4+0] = t0;
            U[r*4+1] = 0.5f*(t0 + t1 + t2);
            U[r*4+2] = 0.5f*(t0 - t1 + t2);
            U[r*4+3] = t2;
        }
    }
    for (int i = tid; i < Hh*9*4; i += nth) {
        int cin = i / 36, r = i - cin*36, j = r >> 2, oc = r & 3;
        float w = (oc < Cc) ? w3[(oc*Hh + cin)*9 + j] : 0.f;
        g_w3t[i] = make_float2(w, w);
    }
}

// ---------------- init -----------------------------------------------------
__global__ void init_kernel(const float* __restrict__ patches)
{
    int i = blockIdx.x * 256 + threadIdx.x;
    if (i < NX) g_x[i] = patches[i];
    if (blockIdx.x < 2) {
        int g = blockIdx.x * 256 + threadIdx.x;
        if (g < Bn*100) g_part[g] = 0.f;
    }
}

__global__ void seps_kernel(const float* __restrict__ eps)
{
    __shared__ float red[1024];
    float s = 0.f;
    for (int i = threadIdx.x; i < NDIM; i += 1024) { float e = eps[i]; s += e * e; }
    red[threadIdx.x] = s; __syncthreads();
    for (int o = 512; o > 0; o >>= 1) {
        if (threadIdx.x < o) red[threadIdx.x] += red[threadIdx.x + o];
        __syncthreads();
    }
    if (threadIdx.x == 0) g_seps = red[0];
}

// ---------------- conv1: Cc->Hh, oc-pair lanes, dup-pixel tile -------------
__global__ __launch_bounds__(256) void conv1_kernel(
    const float* __restrict__ in, float* __restrict__ rawout,
    const float* __restrict__ b1,
    const float* __restrict__ wt, const float* __restrict__ bt,
    float t, int prim)
{
    __shared__ __align__(16) float ws[Cc*9*Hh];       // [cin][j][oc] natural
    __shared__ __align__(16) float2 tile[Cc][18*20];  // {v,v} dup pairs
    __shared__ float evec[64];
    __shared__ float emb[Hh];
    const int tid = threadIdx.x;

    {   // coalesced staging from pre-transposed weights
        const float4* src = (const float4*)g_w1t;
        float4* dst = (float4*)ws;
        for (int i = tid; i < Cc*9*Hh/4; i += 256) dst[i] = src[i];
    }
    if (prim && tid < 64) {
        int k = tid & 31;
        float freq = expf(-0.2971077539347156f * (float)k);  // -ln(1e4)/31 * k
        float a = t * 999.f * freq;
        evec[tid] = (tid < 32) ? sinf(a) : cosf(a);
    }
    __syncthreads();
    if (prim && tid < Hh) {
        float s = bt[tid];
        #pragma unroll
        for (int k = 0; k < 64; k++) s += evec[k] * wt[k*Hh + tid];
        emb[tid] = s;
    }

    const int img = blockIdx.y;
    const int tx0 = (blockIdx.x % 10) * 16, ty0 = (blockIdx.x / 10) * 16;
    const float* base = in + (size_t)img * Cc * PP;
    #pragma unroll
    for (int k = 0; k < 4; k++) {
        int e = tid + k*256;
        if (e < Cc*324) {
            int cin = e / 324, r = e - cin*324;
            int ly = r / 18, lx = r - ly*18;
            int gy = ty0 + ly - 1, gx = tx0 + lx - 1;
            float v = 0.f;
            if (gy >= 0 && gy < Pdim && gx >= 0 && gx < Pdim)
                v = base[cin*PP + gy*Pdim + gx];
            tile[cin][ly*20 + lx] = make_float2(v, v);
        }
    }
    __syncthreads();

    const int quad = tid & 63, ocg = tid >> 6;
    const int qx = (quad & 7)*2, qy = (quad >> 3)*2;

    u64 acc[4][2][2];                         // [oc-pair][py][px]
    #pragma unroll
    for (int a = 0; a < 4; a++)
        #pragma unroll
        for (int p = 0; p < 2; p++) { acc[a][p][0] = 0ULL; acc[a][p][1] = 0ULL; }

    #pragma unroll
    for (int cin = 0; cin < Cc; cin++) {
        u64 ivd[4][4];
        #pragma unroll
        for (int r = 0; r < 4; r++) {
            ulonglong2 A = *(const ulonglong2*)&tile[cin][(qy+r)*20 + qx];
            ulonglong2 B = *(const ulonglong2*)&tile[cin][(qy+r)*20 + qx + 2];
            ivd[r][0] = A.x; ivd[r][1] = A.y; ivd[r][2] = B.x; ivd[r][3] = B.y;
        }
        #pragma unroll
        for (int j = 0; j < 9; j++) {
            const int ky = j/3, kx = j - ky*3;
            const ulonglong2* wq = (const ulonglong2*)&ws[cin*288 + j*32 + ocg*8];
            ulonglong2 wa = wq[0], wb = wq[1];
            u64 w4[4] = {wa.x, wa.y, wb.x, wb.y};
            #pragma unroll
            for (int p2 = 0; p2 < 4; p2++)
                #pragma unroll
                for (int py = 0; py < 2; py++)
                    #pragma unroll
                    for (int px = 0; px < 2; px++)
                        acc[p2][py][px] = ffma2(w4[p2], ivd[py+ky][px+kx], acc[p2][py][px]);
        }
    }

    if (prim) {
        // fused epilogue: act1 = relu(pre1); t1 = (pre1>0)*v1  (v1 is oc-plane)
        #pragma unroll
        for (int p2 = 0; p2 < 4; p2++) {
            int oc0 = ocg*8 + p2*2, oc1 = oc0 + 1;
            float bs0 = b1[oc0] + emb[oc0];
            float bs1 = b1[oc1] + emb[oc1];
            #pragma unroll
            for (int py = 0; py < 2; py++) {
                float l0, h0, l1, h1;
                upk2(acc[p2][py][0], l0, h0);
                upk2(acc[p2][py][1], l1, h1);
                size_t row = (size_t)(ty0+qy+py)*Pdim + tx0+qx;
                float2 v0 = *(const float2*)&g_v1[(size_t)oc0*PP + row];
                float2 v1 = *(const float2*)&g_v1[(size_t)oc1*PP + row];
                float p00 = l0+bs0, p01 = l1+bs0;
                float p10 = h0+bs1, p11 = h1+bs1;
                size_t o0 = ((size_t)img*Hh + oc0)*PP + row;
                size_t o1 = ((size_t)img*Hh + oc1)*PP + row;
                *(float2*)&g_pre1[o0] = make_float2(fmaxf(p00,0.f), fmaxf(p01,0.f));
                *(float2*)&g_pre1[o1] = make_float2(fmaxf(p10,0.f), fmaxf(p11,0.f));
                *(float2*)&g_t1[o0]   = make_float2(p00>0.f?v0.x:0.f, p01>0.f?v0.y:0.f);
                *(float2*)&g_t1[o1]   = make_float2(p10>0.f?v1.x:0.f, p11>0.f?v1.y:0.f);
            }
        }
    } else {
        #pragma unroll
        for (int p2 = 0; p2 < 4; p2++) {
            int oc0 = ocg*8 + p2*2, oc1 = oc0 + 1;
            #pragma unroll
            for (int py = 0; py < 2; py++) {
                float l0, h0, l1, h1;
                upk2(acc[p2][py][0], l0, h0);
                upk2(acc[p2][py][1], l1, h1);
                size_t row = (size_t)(ty0+qy+py)*Pdim + tx0+qx;
                *(float2*)&rawout[((size_t)img*Hh + oc0)*PP + row] = make_float2(l0, l1);
                *(float2*)&rawout[((size_t)img*Hh + oc1)*PP + row] = make_float2(h0, h1);
            }
        }
    }
}

// ---------------- conv2: Winograd F(2x2,3x3), 512 thr, 2 oc/thread --------
// Block outputs 16x8 px, all 32 oc. Thread: m-tile (tid&31) x oc-pair (tid>>5).
// Acc = 2 oc x 8 pos-pairs = 16 u64 (32 regs) -> no spills at 128-reg budget.
// Warp lanes = tiles => U loads broadcast, stores coalesce along x.
// Dynamic smem: U[32][32][16] | tiles[4][10*20] | V[4][32][16]
#define C2_U_FLOATS   (Hh*Hh*16)          // 16384
#define C2_TILE_OFF   C2_U_FLOATS
#define C2_V_OFF      (C2_TILE_OFF + 4*200)
#define C2_SMEM_BYTES ((C2_V_OFF + 4*512) * 4)

__global__ __launch_bounds__(512, 1) void conv2_kernel(
    const float* __restrict__ b2)
{
    extern __shared__ __align__(16) float sm[];
    float* Us    = sm;                    // [cin][oc][16]
    float* tiles = sm + C2_TILE_OFF;      // [4][10*20] scalar halo
    float* Vs    = sm + C2_V_OFF;         // [4][32][16]
    const int tid = threadIdx.x;

    {   // stage U (coalesced float4)
        const float4* s4 = (const float4*)g_w2u;
        float4* d4 = (float4*)Us;
        for (int i = tid; i < C2_U_FLOATS/4; i += 512) d4[i] = s4[i];
    }

    const int img = blockIdx.y;
    const bool tangent = img >= Bn;
    const int b = tangent ? img - Bn : img;
    const int tx0 = (blockIdx.x % 10) * 16, ty0 = (blockIdx.x / 10) * 8;
    const int tile = tid & 31, op = tid >> 5;         // m-tile, oc-pair
    const int mtx = tile & 7, mty = tile >> 3;

    const float* __restrict__ src = (tangent ? g_t1 : g_pre1) + (size_t)b*Hh*PP;

    // halo staging: 10x18 = 180 elems, tid<180
    const bool hasS = tid < 180;
    const int ly = tid / 18, lx = tid - ly*18;
    const int gy = ty0 + ly - 1, gx = tx0 + lx - 1;
    const bool vaS = hasS & (gy>=0) & (gy<Pdim) & (gx>=0) & (gx<Pdim);
    const int offS = gy*Pdim + gx;
    const int sS = ly*20 + lx;

    // V-transform: 64 units (32 tiles x 2 cin-halves), tid<64
    const bool doV = tid < 64;
    const int vTile = tid & 31, vHalf = (tid >> 5) & 1;
    const int vx = (vTile & 7)*2, vy = (vTile >> 3)*2;

    {   // preload cin 0,1 halos
        float c0 = vaS ? src[offS]    : 0.f;
        float c1 = vaS ? src[PP+offS] : 0.f;
        if (hasS) { tiles[sS] = c0; tiles[200 + sS] = c1; }
    }
    __syncthreads();

    u64 M0[8], M1[8];                                  // oc0, oc1 pos-pairs
    #pragma unroll
    for (int p = 0; p < 8; p++) { M0[p] = 0ULL; M1[p] = 0ULL; }

    #pragma unroll 1
    for (int c = 0; c < Hh; c += 2) {
        const bool more = (c + 2) < Hh;
        float nA = 0.f, nB = 0.f;
        if (more) {                                    // prefetch halos c+2,c+3
            nA = vaS ? src[(size_t)(c+2)*PP + offS] : 0.f;
            nB = vaS ? src[(size_t)(c+3)*PP + offS] : 0.f;
        }
        // ---- phase A: input transform V = B^T d B for cins c, c+1 ----
        if (doV) {
            const float* tb = &tiles[((c + vHalf) & 3) * 200];
            float d[4][4];
            #pragma unroll
            for (int r = 0; r < 4; r++)
                #pragma unroll
                for (int cc = 0; cc < 4; cc++)
                    d[r][cc] = tb[(vy+r)*20 + vx+cc];
            float t0[4], t1[4], t2[4], t3[4];
            #pragma unroll
            for (int cc = 0; cc < 4; cc++) {
                t0[cc] = d[0][cc] - d[2][cc];
                t1[cc] = d[1][cc] + d[2][cc];
                t2[cc] = d[2][cc] - d[1][cc];
                t3[cc] = d[1][cc] - d[3][cc];
            }
            float* vo = &Vs[((c + vHalf) & 3)*512 + vTile*16];
            #pragma unroll
            for (int r = 0; r < 4; r++) {
                const float* tr = (r==0)?t0:(r==1)?t1:(r==2)?t2:t3;
                vo[r*4+0] = tr[0] - tr[2];
                vo[r*4+1] = tr[1] + tr[2];
                vo[r*4+2] = tr[2] - tr[1];
                vo[r*4+3] = tr[1] - tr[3];
            }
        }
        __syncthreads();
        // ---- phase B: M += U .* V  (pos-pair FFMA2, 2 oc) ----
        #pragma unroll
        for (int h = 0; h < 2; h++) {
            const int cin = c + h;
            const ulonglong2* Vp = (const ulonglong2*)&Vs[(cin & 3)*512 + tile*16];
            ulonglong2 va = Vp[0], vb = Vp[1], vc = Vp[2], vd = Vp[3];
            u64 v[8] = {va.x, va.y, vb.x, vb.y, vc.x, vc.y, vd.x, vd.y};
            const ulonglong2* Ua =
                (const ulonglong2*)&Us[((size_t)cin*Hh + op*2)*16];
            ulonglong2 a0 = Ua[0], a1 = Ua[1], a2 = Ua[2], a3 = Ua[3];
            M0[0] = ffma2(a0.x, v[0], M0[0]);
            M0[1] = ffma2(a0.y, v[1], M0[1]);
            M0[2] = ffma2(a1.x, v[2], M0[2]);
            M0[3] = ffma2(a1.y, v[3], M0[3]);
            M0[4] = ffma2(a2.x, v[4], M0[4]);
            M0[5] = ffma2(a2.y, v[5], M0[5]);
            M0[6] = ffma2(a3.x, v[6], M0[6]);
            M0[7] = ffma2(a3.y, v[7], M0[7]);
            ulonglong2 b0 = Ua[4], b1v = Ua[5], b2v = Ua[6], b3v = Ua[7];
            M1[0] = ffma2(b0.x,  v[0], M1[0]);
            M1[1] = ffma2(b0.y,  v[1], M1[1]);
            M1[2] = ffma2(b1v.x, v[2], M1[2]);
            M1[3] = ffma2(b1v.y, v[3], M1[3]);
            M1[4] = ffma2(b2v.x, v[4], M1[4]);
            M1[5] = ffma2(b2v.y, v[5], M1[5]);
            M1[6] = ffma2(b3v.x, v[6], M1[6]);
            M1[7] = ffma2(b3v.y, v[7], M1[7]);
        }
        if (more && hasS) {                            // stage halos c+2, c+3
            tiles[((c+2) & 3)*200 + sS] = nA;
            tiles[((c+3) & 3)*200 + sS] = nB;
        }
        __syncthreads();
    }

    // ---- output transform Y = A^T M A, bias, store ----
    const int ox = tx0 + mtx*2, oy = ty0 + mty*2;
    #pragma unroll
    for (int o = 0; o < 2; o++) {
        const u64* M = o ? M1 : M0;
        int oc = op*2 + o;
        float bs = tangent ? 0.f : b2[oc];
        u64 u0p0 = fadd2(fadd2(M[0], M[2]), M[4]);
        u64 u0p1 = fadd2(fadd2(M[1], M[3]), M[5]);
        u64 u1p0 = fsub2(fsub2(M[2], M[4]), M[6]);
        u64 u1p1 = fsub2(fsub2(M[3], M[5]), M[7]);
        float a0,a1,a2,a3, c0,c1,c2,c3;
        upk2(u0p0, a0, a1); upk2(u0p1, a2, a3);
        upk2(u1p0, c0, c1); upk2(u1p1, c2, c3);
        float Y00 = a0 + a1 + a2, Y01 = a1 - a2 - a3;
        float Y10 = c0 + c1 + c2, Y11 = c1 - c2 - c3;
        size_t base = ((size_t)img*Hh + oc)*PP;
        *(float2*)&g_pre2[base + (size_t)oy*Pdim + ox] =
            make_float2(Y00 + bs, Y01 + bs);
        *(float2*)&g_pre2[base + (size_t)(oy+1)*Pdim + ox] =
            make_float2(Y10 + bs, Y11 + bs);
    }
}

// ---------------- conv3: fused primal+tangent, 16x16 tiles, 1 px/thread ----
__global__ __launch_bounds__(256, 2) void conv3_kernel(
    const float* __restrict__ b3,
    const float* __restrict__ eps, const float* __restrict__ xsrc,
    int stage, float hb, float c3, float adt, float accw, float dt6, float lwc3)
{
    __shared__ __align__(16) float2 ws3[Hh*9*4];    // [cin][j][oc pad4] dup {w,w}
    __shared__ __align__(16) float2 tile[4][18*20]; // {relu(p), mask*v}, 4 bufs
    __shared__ float red[256];
    const int tid = threadIdx.x;

    {   // coalesced staging from pre-transposed (already duplicated) weights
        const float4* src = (const float4*)g_w3t;
        float4* dst = (float4*)ws3;
        for (int i = tid; i < Hh*9*4/2; i += 256) dst[i] = src[i];
    }

    const int b = blockIdx.y;                 // batch 0..3
    const int tx0 = (blockIdx.x % 10) * 16, ty0 = (blockIdx.x / 10) * 16;
    const int qx = tid & 15, qy = tid >> 4;   // 1 px per thread

    const float* __restrict__ pb = g_pre2 + (size_t)b*Hh*PP;        // primal pre2
    const float* __restrict__ vb = g_pre2 + (size_t)(Bn+b)*Hh*PP;   // tangent v2

    int offs[2], sidx[2];
    bool vld[2], has[2];
    #pragma unroll
    for (int k = 0; k < 2; k++) {
        int e = tid + k*256;
        has[k] = e < 18*18;
        int r = e / 18, c = e - r*18;
        int gy = ty0 + r - 1, gx = tx0 + c - 1;
        vld[k] = has[k] & (gy>=0) & (gy<Pdim) & (gx>=0) & (gx<Pdim);
        offs[k] = gy*Pdim + gx;
        sidx[k] = r*20 + c;
    }

    #pragma unroll
    for (int k = 0; k < 2; k++) {             // preload cin 0,1
        if (has[k]) {
            float p0 = vld[k] ? pb[offs[k]] : 0.f;
            float v0 = vld[k] ? vb[offs[k]] : 0.f;
            tile[0][sidx[k]] = make_float2(fmaxf(p0, 0.f), p0 > 0.f ? v0 : 0.f);
            float p1 = vld[k] ? pb[PP + offs[k]] : 0.f;
            float v1 = vld[k] ? vb[PP + offs[k]] : 0.f;
            tile[1][sidx[k]] = make_float2(fmaxf(p1, 0.f), p1 > 0.f ? v1 : 0.f);
        }
    }
    __syncthreads();

    u64 acc[3];
    acc[0] = 0ULL; acc[1] = 0ULL; acc[2] = 0ULL;

    #pragma unroll 1
    for (int c = 0; c < Hh; c += 2) {
        const bool more = (c + 2) < Hh;
        float npa[2], nva[2], npb[2], nvb[2];
        if (more) {
            const float* pA = pb + (c+2)*PP;  const float* vA = vb + (c+2)*PP;
            const float* pB = pb + (c+3)*PP;  const float* vB = vb + (c+3)*PP;
            #pragma unroll
            for (int k = 0; k < 2; k++) {
                npa[k] = vld[k] ? pA[offs[k]] : 0.f;
                nva[k] = vld[k] ? vA[offs[k]] : 0.f;
                npb[k] = vld[k] ? pB[offs[k]] : 0.f;
                nvb[k] = vld[k] ? vB[offs[k]] : 0.f;
            }
        }
        const int bA = c & 2;
        #pragma unroll
        for (int h = 0; h < 2; h++) {
            const int cin = c + h;
            const float2* __restrict__ tb = &tile[bA + h][0];
            u64 iv[3][3];
            #pragma unroll
            for (int r = 0; r < 3; r++)
                #pragma unroll
                for (int k = 0; k < 3; k++)
                    iv[r][k] = *(const u64*)&tb[(qy+r)*20 + qx + k];
            #pragma unroll
            for (int j = 0; j < 9; j++) {
                const int ky = j/3, kx = j - ky*3;
                ulonglong2 wq = *(const ulonglong2*)&ws3[(cin*9 + j)*4];
                u64 w2p = *(const u64*)&ws3[(cin*9 + j)*4 + 2];
                acc[0] = ffma2(wq.x, iv[ky][kx], acc[0]);
                acc[1] = ffma2(wq.y, iv[ky][kx], acc[1]);
                acc[2] = ffma2(w2p,  iv[ky][kx], acc[2]);
            }
        }
        if (more) {
            const int sA = (bA + 2) & 3, sB = (bA + 3) & 3;
            #pragma unroll
            for (int k = 0; k < 2; k++) {
                if (has[k]) {
                    tile[sA][sidx[k]] =
                        make_float2(fmaxf(npa[k], 0.f), npa[k] > 0.f ? nva[k] : 0.f);
                    tile[sB][sidx[k]] =
                        make_float2(fmaxf(npb[k], 0.f), npb[k] > 0.f ? nvb[k] : 0.f);
                }
            }
        }
        __syncthreads();
    }

    // fused epilogue: primal -> RK4 combine; tangent -> scaled Hutchinson partial
    float s = 0.f;
    #pragma unroll
    for (int oc = 0; oc < Cc; oc++) {
        float prim, tang;
        upk2(acc[oc], prim, tang);
        size_t idx = ((size_t)b*Cc + oc)*PP + (size_t)(ty0+qy)*Pdim + (tx0+qx);
        float o = prim + b3[oc];
        float k = -hb * xsrc[idx] - c3 * o;
        float a = (stage == 0) ? k : (g_acc[idx] + accw * k);
        if (stage < 3) { g_acc[idx] = a; g_xe[idx] = g_x[idx] + adt * k; }
        else           { g_x[idx] += dt6 * a; }
        s += tang * eps[(size_t)oc*PP + (size_t)(ty0+qy)*Pdim + (tx0+qx)];
    }
    red[tid] = s;
    __syncthreads();
    for (int o = 128; o > 0; o >>= 1) {
        if (tid < o) red[tid] += red[tid + o];
        __syncthreads();
    }
    if (tid == 0) g_part[b*100 + blockIdx.x] -= lwc3 * red[0];  // -= : sign folded
}

// ---------------- final: prior logp + divergence finish + bpd --------------
__global__ void final_kernel(float* __restrict__ out, float sumLwHb)
{
    __shared__ float red[1024];
    int b = blockIdx.x;
    float s = 0.f;
    for (int i = threadIdx.x; i < NDIM; i += 1024) {
        float z = g_x[(size_t)b * NDIM + i]; s += z * z;
    }
    red[threadIdx.x] = s; __syncthreads();
    for (int o = 512; o > 0; o >>= 1) {
        if (threadIdx.x < o) red[threadIdx.x] += red[threadIdx.x + o];
        __syncthreads();
    }
    if (threadIdx.x == 0) {
        float dsum = 0.f;
        for (int k = 0; k < 100; k++) dsum += g_part[b*100 + k];
        float lp = -sumLwHb * g_seps + dsum;
        float prior = -0.5f * (float)NDIM * 1.8378770664093453f - 0.5f * red[0];
        out[b] = -(prior + lp) * 1.4426950408889634f / (float)NDIM;
    }
}

// ---------------- host orchestration (graph-capturable) --------------------
extern "C" void kernel_launch(void* const* d_in, const int* in_sizes, int n_in,
                              void* d_out, int out_size)
{
    const float* patches = (const float*)d_in[0];
    const float* eps     = (const float*)d_in[1];
    const float* w1 = (const float*)d_in[2];
    const float* b1 = (const float*)d_in[3];
    const float* wt = (const float*)d_in[4];
    const float* bt = (const float*)d_in[5];
    const float* w2 = (const float*)d_in[6];
    const float* b2 = (const float*)d_in[7];
    const float* w3 = (const float*)d_in[8];
    const float* b3 = (const float*)d_in[9];
    float* out = (float*)d_out;

    float *p_x, *p_xe, *p_v1;
    cudaGetSymbolAddress((void**)&p_x,  g_x);
    cudaGetSymbolAddress((void**)&p_xe, g_xe);
    cudaGetSymbolAddress((void**)&p_v1, g_v1);

    cudaFuncSetAttribute(conv2_kernel,
                         cudaFuncAttributeMaxDynamicSharedMemorySize,
                         C2_SMEM_BYTES);

    prep_weights<<<40, 256>>>(w1, w2, w3);
    init_kernel<<<NX/256, 256>>>(patches);
    seps_kernel<<<1, 1024>>>(eps);
    // loop-invariant tangent through layer 1: v1 = conv1(eps), no bias/emb
    conv1_kernel<<<dim3(100, 1), 256>>>(eps, p_v1, b1, wt, bt, 0.f, 0);

    const float dtf = (1.0f - 1e-5f) / 10.0f;
    double sumLwHb = 0.0;
    for (int i = 0; i < 10; i++) {
        float t0 = 1e-5f + dtf * (float)i;
        float tstage[4] = { t0, t0 + 0.5f*dtf, t0 + 0.5f*dtf, t0 + dtf };
        float adt[4]    = { 0.5f*dtf, 0.5f*dtf, dtf, 0.f };
        float accw[4]   = { 1.f, 2.f, 2.f, 1.f };
        float lpw[4]    = { dtf/6.f, dtf/3.f, dtf/3.f, dtf/6.f };
        for (int s = 0; s < 4; s++) {
            double t    = (double)tstage[s];
            double beta = 0.1 + t * 19.9;
            double lmc  = -0.25 * t * t * 19.9 - 0.05 * t;
            float  hb   = (float)(0.5 * beta);
            // 0.5*g2/std == 0.5*beta*(1+e^{2*lmc})  (exact, cancellation-free)
            float  c3   = (float)(0.5 * beta * (1.0 + exp(2.0 * lmc)));
            sumLwHb += (double)lpw[s] * (double)hb;

            const float* xin = (s == 0) ? p_x : p_xe;
            conv1_kernel<<<dim3(100, Bn), 256>>>(xin, nullptr, b1, wt, bt, tstage[s], 1);
            conv2_kernel<<<dim3(200, 2*Bn), 512, C2_SMEM_BYTES>>>(b2);
            conv3_kernel<<<dim3(100, Bn), 256>>>(b3, eps, xin,
                                                 s, hb, c3, adt[s], accw[s], dtf/6.f,
                                                 lpw[s] * c3);
        }
    }
    final_kernel<<<Bn, 1024>>>(out, (float)sumLwHb);
}

// round 17
// speedup vs baseline: 2.6493x; 2.6493x over previous
#include <cuda_runtime.h>
#include <cmath>

#define Pdim 160
#define PP (Pdim*Pdim)          // 25600
#define Bn 4
#define Cc 3
#define Hh 32
#define NDIM (Cc*PP)            // 76800
#define NX (Bn*NDIM)            // 307200

typedef unsigned long long u64;

__device__ __forceinline__ void upk2(u64 v, float& lo, float& hi) {
    asm("mov.b64 {%0,%1},%2;" : "=f"(lo), "=f"(hi) : "l"(v));
}
// packed fp32x2 FMA (SASS FFMA2): 2 exact fp32 FMAs per issue slot
__device__ __forceinline__ u64 ffma2(u64 a, u64 b, u64 c) {
    u64 d; asm("fma.rn.f32x2 %0,%1,%2,%3;" : "=l"(d) : "l"(a), "l"(b), "l"(c));
    return d;
}

// ---------------- scratch (static device globals; no allocs allowed) -------
__device__ float g_x[NX];
__device__ float g_xe[NX];
__device__ float g_acc[NX];
__device__ float g_pre1[Bn*Hh*PP];        // act1 = relu(conv1 pre-act), primal
__device__ float g_t1[Bn*Hh*PP];          // t1 = mask(pre1) * v1, tangent
__device__ float g_v1[Hh*PP];             // conv1(eps), loop-invariant tangent
__device__ float g_pre2[2*Bn*Hh*PP];      // [0..4): primal pre2, [4..8): tangent v2
__device__ float g_part[Bn*100];          // scaled divergence partials (accumulated)
__device__ float g_seps;
// pre-transposed weights (smem-layout; filled once per replay)
__device__ float  g_w1t[Cc*9*Hh];         // [cin][j][oc]
__device__ float  g_w2t[Hh*9*Hh];         // [cin][j][oc]
__device__ float2 g_w3t[Hh*9*4];          // [cin][j][oc pad4] dup {w,w}

// ---------------- weight transpose (once per replay; coalesced writes) -----
__global__ void prep_weights(const float* __restrict__ w1,
                             const float* __restrict__ w2,
                             const float* __restrict__ w3)
{
    int tid = blockIdx.x * 256 + threadIdx.x;
    int nth = gridDim.x * 256;
    for (int i = tid; i < Cc*9*Hh; i += nth) {
        int cin = i / 288, r = i - cin*288, j = r >> 5, oc = r & 31;
        g_w1t[i] = w1[(oc*Cc + cin)*9 + j];
    }
    for (int i = tid; i < Hh*9*Hh; i += nth) {
        int cin = i / 288, r = i - cin*288, j = r >> 5, oc = r & 31;
        g_w2t[i] = w2[(oc*Hh + cin)*9 + j];
    }
    for (int i = tid; i < Hh*9*4; i += nth) {
        int cin = i / 36, r = i - cin*36, j = r >> 2, oc = r & 3;
        float w = (oc < Cc) ? w3[(oc*Hh + cin)*9 + j] : 0.f;
        g_w3t[i] = make_float2(w, w);
    }
}

// ---------------- init -----------------------------------------------------
__global__ void init_kernel(const float* __restrict__ patches)
{
    int i = blockIdx.x * 256 + threadIdx.x;
    if (i < NX) g_x[i] = patches[i];
    if (blockIdx.x < 2) {
        int g = blockIdx.x * 256 + threadIdx.x;
        if (g < Bn*100) g_part[g] = 0.f;
    }
}

__global__ void seps_kernel(const float* __restrict__ eps)
{
    __shared__ float red[1024];
    float s = 0.f;
    for (int i = threadIdx.x; i < NDIM; i += 1024) { float e = eps[i]; s += e * e; }
    red[threadIdx.x] = s; __syncthreads();
    for (int o = 512; o > 0; o >>= 1) {
        if (threadIdx.x < o) red[threadIdx.x] += red[threadIdx.x + o];
        __syncthreads();
    }
    if (threadIdx.x == 0) g_seps = red[0];
}

// ---------------- conv1: Cc->Hh, oc-pair lanes, dup-pixel tile -------------
// FFMA2 lanes = (oc, oc+1); weights naturally packed, pixels stored {x,x}.
// prim==1: writes act1 = relu(pre1) and t1 = mask(pre1)*v1 (fused epilogue).
// prim==0: writes raw conv output (used once, to build v1 from eps).
__global__ __launch_bounds__(256) void conv1_kernel(
    const float* __restrict__ in, float* __restrict__ rawout,
    const float* __restrict__ b1,
    const float* __restrict__ wt, const float* __restrict__ bt,
    float t, int prim)
{
    __shared__ __align__(16) float ws[Cc*9*Hh];       // [cin][j][oc] natural
    __shared__ __align__(16) float2 tile[Cc][18*20];  // {v,v} dup pairs
    __shared__ float evec[64];
    __shared__ float emb[Hh];
    const int tid = threadIdx.x;

    {   // coalesced staging from pre-transposed weights
        const float4* src = (const float4*)g_w1t;
        float4* dst = (float4*)ws;
        for (int i = tid; i < Cc*9*Hh/4; i += 256) dst[i] = src[i];
    }
    if (prim && tid < 64) {
        int k = tid & 31;
        float freq = expf(-0.2971077539347156f * (float)k);  // -ln(1e4)/31 * k
        float a = t * 999.f * freq;
        evec[tid] = (tid < 32) ? sinf(a) : cosf(a);
    }
    __syncthreads();
    if (prim && tid < Hh) {
        float s = bt[tid];
        #pragma unroll
        for (int k = 0; k < 64; k++) s += evec[k] * wt[k*Hh + tid];
        emb[tid] = s;
    }

    const int img = blockIdx.y;
    const int tx0 = (blockIdx.x % 10) * 16, ty0 = (blockIdx.x / 10) * 16;
    const float* base = in + (size_t)img * Cc * PP;
    #pragma unroll
    for (int k = 0; k < 4; k++) {
        int e = tid + k*256;
        if (e < Cc*324) {
            int cin = e / 324, r = e - cin*324;
            int ly = r / 18, lx = r - ly*18;
            int gy = ty0 + ly - 1, gx = tx0 + lx - 1;
            float v = 0.f;
            if (gy >= 0 && gy < Pdim && gx >= 0 && gx < Pdim)
                v = base[cin*PP + gy*Pdim + gx];
            tile[cin][ly*20 + lx] = make_float2(v, v);
        }
    }
    __syncthreads();

    const int quad = tid & 63, ocg = tid >> 6;
    const int qx = (quad & 7)*2, qy = (quad >> 3)*2;

    u64 acc[4][2][2];                         // [oc-pair][py][px]
    #pragma unroll
    for (int a = 0; a < 4; a++)
        #pragma unroll
        for (int p = 0; p < 2; p++) { acc[a][p][0] = 0ULL; acc[a][p][1] = 0ULL; }

    #pragma unroll
    for (int cin = 0; cin < Cc; cin++) {
        u64 ivd[4][4];
        #pragma unroll
        for (int r = 0; r < 4; r++) {
            ulonglong2 A = *(const ulonglong2*)&tile[cin][(qy+r)*20 + qx];
            ulonglong2 B = *(const ulonglong2*)&tile[cin][(qy+r)*20 + qx + 2];
            ivd[r][0] = A.x; ivd[r][1] = A.y; ivd[r][2] = B.x; ivd[r][3] = B.y;
        }
        #pragma unroll
        for (int j = 0; j < 9; j++) {
            const int ky = j/3, kx = j - ky*3;
            const ulonglong2* wq = (const ulonglong2*)&ws[cin*288 + j*32 + ocg*8];
            ulonglong2 wa = wq[0], wb = wq[1];
            u64 w4[4] = {wa.x, wa.y, wb.x, wb.y};
            #pragma unroll
            for (int p2 = 0; p2 < 4; p2++)
                #pragma unroll
                for (int py = 0; py < 2; py++)
                    #pragma unroll
                    for (int px = 0; px < 2; px++)
                        acc[p2][py][px] = ffma2(w4[p2], ivd[py+ky][px+kx], acc[p2][py][px]);
        }
    }

    if (prim) {
        // fused epilogue: act1 = relu(pre1); t1 = (pre1>0)*v1  (v1 is oc-plane)
        #pragma unroll
        for (int p2 = 0; p2 < 4; p2++) {
            int oc0 = ocg*8 + p2*2, oc1 = oc0 + 1;
            float bs0 = b1[oc0] + emb[oc0];
            float bs1 = b1[oc1] + emb[oc1];
            #pragma unroll
            for (int py = 0; py < 2; py++) {
                float l0, h0, l1, h1;
                upk2(acc[p2][py][0], l0, h0);
                upk2(acc[p2][py][1], l1, h1);
                size_t row = (size_t)(ty0+qy+py)*Pdim + tx0+qx;
                float2 v0 = *(const float2*)&g_v1[(size_t)oc0*PP + row];
                float2 v1 = *(const float2*)&g_v1[(size_t)oc1*PP + row];
                float p00 = l0+bs0, p01 = l1+bs0;   // oc0 @ px0,px1
                float p10 = h0+bs1, p11 = h1+bs1;   // oc1 @ px0,px1
                size_t o0 = ((size_t)img*Hh + oc0)*PP + row;
                size_t o1 = ((size_t)img*Hh + oc1)*PP + row;
                *(float2*)&g_pre1[o0] = make_float2(fmaxf(p00,0.f), fmaxf(p01,0.f));
                *(float2*)&g_pre1[o1] = make_float2(fmaxf(p10,0.f), fmaxf(p11,0.f));
                *(float2*)&g_t1[o0]   = make_float2(p00>0.f?v0.x:0.f, p01>0.f?v0.y:0.f);
                *(float2*)&g_t1[o1]   = make_float2(p10>0.f?v1.x:0.f, p11>0.f?v1.y:0.f);
            }
        }
    } else {
        #pragma unroll
        for (int p2 = 0; p2 < 4; p2++) {
            int oc0 = ocg*8 + p2*2, oc1 = oc0 + 1;
            #pragma unroll
            for (int py = 0; py < 2; py++) {
                float l0, h0, l1, h1;
                upk2(acc[p2][py][0], l0, h0);
                upk2(acc[p2][py][1], l1, h1);
                size_t row = (size_t)(ty0+qy+py)*Pdim + tx0+qx;
                *(float2*)&rawout[((size_t)img*Hh + oc0)*PP + row] = make_float2(l0, l1);
                *(float2*)&rawout[((size_t)img*Hh + oc1)*PP + row] = make_float2(h0, h1);
            }
        }
    }
}

// ---------------- conv2: Hh->Hh, 128-thr blocks, 16x8 tiles, 4-buf pipe ----
// Uniform source: act1 (primal imgs) or t1 (tangent imgs); single load/point.
__global__ __launch_bounds__(128) void conv2_kernel(
    const float* __restrict__ b2)
{
    __shared__ __align__(16) float ws[Hh*9*Hh];       // [cin][j][oc] 36KB
    __shared__ __align__(16) float2 tile[4][10*20];   // {v,v} dup pairs, 4 bufs
    const int tid = threadIdx.x;

    {   // coalesced staging from pre-transposed weights
        const float4* src4 = (const float4*)g_w2t;
        float4* dst = (float4*)ws;
        for (int i = tid; i < Hh*9*Hh/4; i += 128) dst[i] = src4[i];
    }

    const int img = blockIdx.y;
    const bool tangent = img >= Bn;
    const int b = tangent ? img - Bn : img;
    const int tx0 = (blockIdx.x % 10) * 16, ty0 = (blockIdx.x / 10) * 8;
    const int quad = tid & 31, ocg = tid >> 5;        // 4 oc-groups x 8 oc
    const int qx = (quad & 7)*2, qy = (quad >> 3)*2;  // 8x-slots x 4y-slots

    const float* __restrict__ src = (tangent ? g_t1 : g_pre1) + (size_t)b*Hh*PP;

    const int e0 = tid;                               // 0..127 of 10*18=180
    const int ly0 = e0/18, lx0 = e0 - ly0*18;
    const int gy0 = ty0+ly0-1, gx0 = tx0+lx0-1;
    const bool va0 = (gy0>=0) & (gy0<Pdim) & (gx0>=0) & (gx0<Pdim);
    const int off0 = gy0*Pdim + gx0, s0 = ly0*20 + lx0;
    const int e1 = tid + 128;
    const bool has1 = e1 < 180;
    const int ly1 = e1/18, lx1 = e1 - ly1*18;
    const int gy1 = ty0+ly1-1, gx1 = tx0+lx1-1;
    const bool va1 = has1 & (gy1>=0) & (gy1<Pdim) & (gx1>=0) & (gx1<Pdim);
    const int off1 = gy1*Pdim + gx1, s1 = ly1*20 + lx1;

    {   // preload cin 0,1
        float c0 = va0 ? src[off0]    : 0.f;
        float c1 = va1 ? src[off1]    : 0.f;
        float d0 = va0 ? src[PP+off0] : 0.f;
        float d1 = va1 ? src[PP+off1] : 0.f;
        tile[0][s0] = make_float2(c0, c0);
        if (has1) tile[0][s1] = make_float2(c1, c1);
        tile[1][s0] = make_float2(d0, d0);
        if (has1) tile[1][s1] = make_float2(d1, d1);
    }
    __syncthreads();

    u64 acc[4][2][2];                         // [oc-pair][py][px]
    #pragma unroll
    for (int a = 0; a < 4; a++)
        #pragma unroll
        for (int p = 0; p < 2; p++) { acc[a][p][0] = 0ULL; acc[a][p][1] = 0ULL; }

    #pragma unroll 1
    for (int c = 0; c < Hh; c += 2) {
        const bool more = (c + 2) < Hh;
        float n0a=0.f, n1a=0.f, n0b=0.f, n1b=0.f;
        if (more) {                           // prefetch planes c+2, c+3
            const float* pA = src + (size_t)(c+2)*PP;
            const float* pB = src + (size_t)(c+3)*PP;
            n0a = va0 ? pA[off0] : 0.f;
            n1a = va1 ? pA[off1] : 0.f;
            n0b = va0 ? pB[off0] : 0.f;
            n1b = va1 ? pB[off1] : 0.f;
        }
        const int bA = c & 2;                 // 0,2,0,2,...
        #pragma unroll
        for (int h = 0; h < 2; h++) {         // two cin planes back-to-back
            const int cin = c + h;
            const float2* __restrict__ tb = &tile[bA + h][0];
            u64 ivd[4][4];
            #pragma unroll
            for (int r = 0; r < 4; r++) {
                ulonglong2 A = *(const ulonglong2*)&tb[(qy+r)*20 + qx];
                ulonglong2 B = *(const ulonglong2*)&tb[(qy+r)*20 + qx + 2];
                ivd[r][0] = A.x; ivd[r][1] = A.y; ivd[r][2] = B.x; ivd[r][3] = B.y;
            }
            #pragma unroll
            for (int j = 0; j < 9; j++) {
                const int ky = j/3, kx = j - ky*3;
                const ulonglong2* wq = (const ulonglong2*)&ws[cin*288 + j*32 + ocg*8];
                ulonglong2 wa = wq[0], wb = wq[1];
                u64 w4[4] = {wa.x, wa.y, wb.x, wb.y};
                #pragma unroll
                for (int p2 = 0; p2 < 4; p2++)
                    #pragma unroll
                    for (int py = 0; py < 2; py++)
                        #pragma unroll
                        for (int px = 0; px < 2; px++)
                            acc[p2][py][px] = ffma2(w4[p2], ivd[py+ky][px+kx], acc[p2][py][px]);
            }
        }
        if (more) {                           // store into buffers read last iter
            const int sA = (bA + 2) & 3, sB = (bA + 3) & 3;
            tile[sA][s0] = make_float2(n0a, n0a);
            if (has1) tile[sA][s1] = make_float2(n1a, n1a);
            tile[sB][s0] = make_float2(n0b, n0b);
            if (has1) tile[sB][s1] = make_float2(n1b, n1b);
        }
        __syncthreads();                      // one barrier per 2 cin
    }

    #pragma unroll
    for (int p2 = 0; p2 < 4; p2++) {
        int oc0 = ocg*8 + p2*2, oc1 = oc0 + 1;
        float bs0 = tangent ? 0.f : b2[oc0];
        float bs1 = tangent ? 0.f : b2[oc1];
        #pragma unroll
        for (int py = 0; py < 2; py++) {
            float l0, h0, l1, h1;
            upk2(acc[p2][py][0], l0, h0);
            upk2(acc[p2][py][1], l1, h1);
            size_t row = (size_t)(ty0+qy+py)*Pdim + tx0+qx;
            *(float2*)&g_pre2[((size_t)img*Hh + oc0)*PP + row] = make_float2(l0+bs0, l1+bs0);
            *(float2*)&g_pre2[((size_t)img*Hh + oc1)*PP + row] = make_float2(h0+bs1, h1+bs1);
        }
    }
}

// ---------------- conv3: fused primal+tangent, 16x16 tiles, 1 px/thread ----
// lane0 = primal (relu), lane1 = tangent (masked); same weight both lanes.
__global__ __launch_bounds__(256, 2) void conv3_kernel(
    const float* __restrict__ b3,
    const float* __restrict__ eps, const float* __restrict__ xsrc,
    int stage, float hb, float c3, float adt, float accw, float dt6, float lwc3)
{
    __shared__ __align__(16) float2 ws3[Hh*9*4];    // [cin][j][oc pad4] dup {w,w}
    __shared__ __align__(16) float2 tile[4][18*20]; // {relu(p), mask*v}, 4 bufs
    __shared__ float red[256];
    const int tid = threadIdx.x;

    {   // coalesced staging from pre-transposed (already duplicated) weights
        const float4* src = (const float4*)g_w3t;
        float4* dst = (float4*)ws3;
        for (int i = tid; i < Hh*9*4/2; i += 256) dst[i] = src[i];
    }

    const int b = blockIdx.y;                 // batch 0..3
    const int tx0 = (blockIdx.x % 10) * 16, ty0 = (blockIdx.x / 10) * 16;
    const int qx = tid & 15, qy = tid >> 4;   // 1 px per thread

    const float* __restrict__ pb = g_pre2 + (size_t)b*Hh*PP;        // primal pre2
    const float* __restrict__ vb = g_pre2 + (size_t)(Bn+b)*Hh*PP;   // tangent v2

    int offs[2], sidx[2];
    bool vld[2], has[2];
    #pragma unroll
    for (int k = 0; k < 2; k++) {
        int e = tid + k*256;
        has[k] = e < 18*18;
        int r = e / 18, c = e - r*18;
        int gy = ty0 + r - 1, gx = tx0 + c - 1;
        vld[k] = has[k] & (gy>=0) & (gy<Pdim) & (gx>=0) & (gx<Pdim);
        offs[k] = gy*Pdim + gx;
        sidx[k] = r*20 + c;
    }

    #pragma unroll
    for (int k = 0; k < 2; k++) {             // preload cin 0,1
        if (has[k]) {
            float p0 = vld[k] ? pb[offs[k]] : 0.f;
            float v0 = vld[k] ? vb[offs[k]] : 0.f;
            tile[0][sidx[k]] = make_float2(fmaxf(p0, 0.f), p0 > 0.f ? v0 : 0.f);
            float p1 = vld[k] ? pb[PP + offs[k]] : 0.f;
            float v1 = vld[k] ? vb[PP + offs[k]] : 0.f;
            tile[1][sidx[k]] = make_float2(fmaxf(p1, 0.f), p1 > 0.f ? v1 : 0.f);
        }
    }
    __syncthreads();

    u64 acc[3];
    acc[0] = 0ULL; acc[1] = 0ULL; acc[2] = 0ULL;

    #pragma unroll 1
    for (int c = 0; c < Hh; c += 2) {
        const bool more = (c + 2) < Hh;
        float npa[2], nva[2], npb[2], nvb[2];
        if (more) {
            const float* pA = pb + (c+2)*PP;  const float* vA = vb + (c+2)*PP;
            const float* pB = pb + (c+3)*PP;  const float* vB = vb + (c+3)*PP;
            #pragma unroll
            for (int k = 0; k < 2; k++) {
                npa[k] = vld[k] ? pA[offs[k]] : 0.f;
                nva[k] = vld[k] ? vA[offs[k]] : 0.f;
                npb[k] = vld[k] ? pB[offs[k]] : 0.f;
                nvb[k] = vld[k] ? vB[offs[k]] : 0.f;
            }
        }
        const int bA = c & 2;
        #pragma unroll
        for (int h = 0; h < 2; h++) {
            const int cin = c + h;
            const float2* __restrict__ tb = &tile[bA + h][0];
            u64 iv[3][3];
            #pragma unroll
            for (int r = 0; r < 3; r++)
                #pragma unroll
                for (int k = 0; k < 3; k++)
                    iv[r][k] = *(const u64*)&tb[(qy+r)*20 + qx + k];
            #pragma unroll
            for (int j = 0; j < 9; j++) {
                const int ky = j/3, kx = j - ky*3;
                ulonglong2 wq = *(const ulonglong2*)&ws3[(cin*9 + j)*4];
                u64 w2p = *(const u64*)&ws3[(cin*9 + j)*4 + 2];
                acc[0] = ffma2(wq.x, iv[ky][kx], acc[0]);
                acc[1] = ffma2(wq.y, iv[ky][kx], acc[1]);
                acc[2] = ffma2(w2p,  iv[ky][kx], acc[2]);
            }
        }
        if (more) {
            const int sA = (bA + 2) & 3, sB = (bA + 3) & 3;
            #pragma unroll
            for (int k = 0; k < 2; k++) {
                if (has[k]) {
                    tile[sA][sidx[k]] =
                        make_float2(fmaxf(npa[k], 0.f), npa[k] > 0.f ? nva[k] : 0.f);
                    tile[sB][sidx[k]] =
                        make_float2(fmaxf(npb[k], 0.f), npb[k] > 0.f ? nvb[k] : 0.f);
                }
            }
        }
        __syncthreads();
    }

    // fused epilogue: primal -> RK4 combine; tangent -> scaled Hutchinson partial
    float s = 0.f;
    #pragma unroll
    for (int oc = 0; oc < Cc; oc++) {
        float prim, tang;
        upk2(acc[oc], prim, tang);
        size_t idx = ((size_t)b*Cc + oc)*PP + (size_t)(ty0+qy)*Pdim + (tx0+qx);
        float o = prim + b3[oc];
        float k = -hb * xsrc[idx] - c3 * o;
        float a = (stage == 0) ? k : (g_acc[idx] + accw * k);
        if (stage < 3) { g_acc[idx] = a; g_xe[idx] = g_x[idx] + adt * k; }
        else           { g_x[idx] += dt6 * a; }
        s += tang * eps[(size_t)oc*PP + (size_t)(ty0+qy)*Pdim + (tx0+qx)];
    }
    red[tid] = s;
    __syncthreads();
    for (int o = 128; o >= 32; o >>= 1) {
        if (tid < o) red[tid] += red[tid + o];
        __syncthreads();
    }
    if (tid < 32) {
        float v = red[tid];
        #pragma unroll
        for (int o = 16; o > 0; o >>= 1) v += __shfl_down_sync(0xffffffffu, v, o);
        if (tid == 0) g_part[b*100 + blockIdx.x] -= lwc3 * v;  // -= : sign folded
    }
}

// ---------------- final: prior logp + divergence finish + bpd --------------
__global__ void final_kernel(float* __restrict__ out, float sumLwHb)
{
    __shared__ float red[1024];
    int b = blockIdx.x;
    float s = 0.f;
    for (int i = threadIdx.x; i < NDIM; i += 1024) {
        float z = g_x[(size_t)b * NDIM + i]; s += z * z;
    }
    red[threadIdx.x] = s; __syncthreads();
    for (int o = 512; o > 0; o >>= 1) {
        if (threadIdx.x < o) red[threadIdx.x] += red[threadIdx.x + o];
        __syncthreads();
    }
    if (threadIdx.x == 0) {
        float dsum = 0.f;
        for (int k = 0; k < 100; k++) dsum += g_part[b*100 + k];
        float lp = -sumLwHb * g_seps + dsum;
        float prior = -0.5f * (float)NDIM * 1.8378770664093453f - 0.5f * red[0];
        out[b] = -(prior + lp) * 1.4426950408889634f / (float)NDIM;
    }
}

// ---------------- host orchestration (graph-capturable) --------------------
extern "C" void kernel_launch(void* const* d_in, const int* in_sizes, int n_in,
                              void* d_out, int out_size)
{
    const float* patches = (const float*)d_in[0];
    const float* eps     = (const float*)d_in[1];
    const float* w1 = (const float*)d_in[2];
    const float* b1 = (const float*)d_in[3];
    const float* wt = (const float*)d_in[4];
    const float* bt = (const float*)d_in[5];
    const float* w2 = (const float*)d_in[6];
    const float* b2 = (const float*)d_in[7];
    const float* w3 = (const float*)d_in[8];
    const float* b3 = (const float*)d_in[9];
    float* out = (float*)d_out;

    float *p_x, *p_xe, *p_v1;
    cudaGetSymbolAddress((void**)&p_x,  g_x);
    cudaGetSymbolAddress((void**)&p_xe, g_xe);
    cudaGetSymbolAddress((void**)&p_v1, g_v1);

    prep_weights<<<40, 256>>>(w1, w2, w3);
    init_kernel<<<NX/256, 256>>>(patches);
    seps_kernel<<<1, 1024>>>(eps);
    // loop-invariant tangent through layer 1: v1 = conv1(eps), no bias/emb
    conv1_kernel<<<dim3(100, 1), 256>>>(eps, p_v1, b1, wt, bt, 0.f, 0);

    const float dtf = (1.0f - 1e-5f) / 10.0f;
    double sumLwHb = 0.0;
    for (int i = 0; i < 10; i++) {
        float t0 = 1e-5f + dtf * (float)i;
        float tstage[4] = { t0, t0 + 0.5f*dtf, t0 + 0.5f*dtf, t0 + dtf };
        float adt[4]    = { 0.5f*dtf, 0.5f*dtf, dtf, 0.f };
        float accw[4]   = { 1.f, 2.f, 2.f, 1.f };
        float lpw[4]    = { dtf/6.f, dtf/3.f, dtf/3.f, dtf/6.f };
        for (int s = 0; s < 4; s++) {
            double t    = (double)tstage[s];
            double beta = 0.1 + t * 19.9;
            double lmc  = -0.25 * t * t * 19.9 - 0.05 * t;
            float  hb   = (float)(0.5 * beta);
            // 0.5*g2/std == 0.5*beta*(1+e^{2*lmc})  (exact, cancellation-free)
            float  c3   = (float)(0.5 * beta * (1.0 + exp(2.0 * lmc)));
            sumLwHb += (double)lpw[s] * (double)hb;

            const float* xin = (s == 0) ? p_x : p_xe;
            conv1_kernel<<<dim3(100, Bn),   256>>>(xin, nullptr, b1, wt, bt, tstage[s], 1);
            conv2_kernel<<<dim3(200, 2*Bn), 128>>>(b2);
            conv3_kernel<<<dim3(100, Bn),   256>>>(b3, eps, xin,
                                                   s, hb, c3, adt[s], accw[s], dtf/6.f,
                                                   lpw[s] * c3);
        }
    }
    final_kernel<<<Bn, 1024>>>(out, (float)sumLwHb);
}